// round 5
// baseline (speedup 1.0000x reference)
#include <cuda_runtime.h>
#include <cstdint>

#define Bb 8
#define Nn 512
#define Ff 128
#define Hh 4
#define Cc 64
#define OUTW (2*Hh*Cc)   // 512

// fp32 feats scratch [B,H,N,C] (pre-activation, needed by attention)
__device__ float g_feats[(size_t)Bb*Hh*Nn*Cc];

// ---------------------------------------------------------------------------
// Kernel 1: feats[b,h,n,c] = sum_f X[b,n,f] * K[h,f,c]
//   also writes out[b,n, h*64+c] = relu(feats)   (the "emb" half, final relu)
// grid (N/64, H, B), 256 threads, 64x64 tile, 4x4 microtile
// ---------------------------------------------------------------------------
__global__ void k1_proj(const float* __restrict__ X,
                        const float* __restrict__ kernels,
                        float* __restrict__ out) {
    extern __shared__ float sm1[];
    float* Ks = sm1;               // 128*64 floats
    float* Xs = sm1 + Ff * Cc;     // 64 rows * 132 (pad) floats

    const int tid = threadIdx.x;
    const int tx = tid & 15;
    const int ty = tid >> 4;
    const int n0 = blockIdx.x * 64;
    const int h  = blockIdx.y;
    const int b  = blockIdx.z;

    // load kernel[h] : 2048 float4
    {
        const float4* src = reinterpret_cast<const float4*>(kernels + (size_t)h * Ff * Cc);
        float4* dst = reinterpret_cast<float4*>(Ks);
        #pragma unroll
        for (int it = 0; it < 8; ++it) dst[tid + it * 256] = src[tid + it * 256];
    }
    // load X tile 64x128 into padded rows (stride 132 floats = 33 float4)
    {
        #pragma unroll
        for (int it = 0; it < 8; ++it) {
            int idx = tid + it * 256;      // float4 index, 2048 total
            int r = idx >> 5, c4 = idx & 31;
            float4 v = reinterpret_cast<const float4*>(
                X + ((size_t)(b * Nn + n0 + r)) * Ff)[c4];
            *reinterpret_cast<float4*>(&Xs[r * 132 + c4 * 4]) = v;
        }
    }
    __syncthreads();

    float acc[4][4];
    #pragma unroll
    for (int i = 0; i < 4; ++i)
        #pragma unroll
        for (int j = 0; j < 4; ++j) acc[i][j] = 0.f;

    const int c0 = tx * 4;
    #pragma unroll 8
    for (int f = 0; f < Ff; ++f) {
        float4 kv = *reinterpret_cast<const float4*>(&Ks[f * Cc + c0]);
        float xa[4];
        #pragma unroll
        for (int i = 0; i < 4; ++i) xa[i] = Xs[(ty + 16 * i) * 132 + f];
        #pragma unroll
        for (int i = 0; i < 4; ++i) {
            acc[i][0] += xa[i] * kv.x;
            acc[i][1] += xa[i] * kv.y;
            acc[i][2] += xa[i] * kv.z;
            acc[i][3] += xa[i] * kv.w;
        }
    }

    const size_t bh = (size_t)b * Hh + h;
    #pragma unroll
    for (int i = 0; i < 4; ++i) {
        int n = n0 + ty + 16 * i;
        float4 v = make_float4(acc[i][0], acc[i][1], acc[i][2], acc[i][3]);
        *reinterpret_cast<float4*>(&g_feats[(bh * Nn + n) * Cc + c0]) = v;
        float4 r = make_float4(fmaxf(v.x, 0.f), fmaxf(v.y, 0.f),
                               fmaxf(v.z, 0.f), fmaxf(v.w, 0.f));
        *reinterpret_cast<float4*>(out + ((size_t)(b * Nn + n)) * OUTW + h * Cc + c0) = r;
    }
}

// ---------------------------------------------------------------------------
// Kernel 2: masked-softmax attention + sparse weighted sum + bias + relu
//   out[b,i, 256 + h*64 + c] = relu( sum_j attn(i,j)*feats[b,h,j,c] + bias[h,c] )
// grid (4 row-chunks, H, B), 512 threads (16 warps), warp-per-row.
// SMEM: feats (512x66 padded) + a_s/a_n (512 each) + per-warp compact buffers
// ---------------------------------------------------------------------------
#define ROWS 128
#define FPAD 66

__global__ void k2_attn(const float* __restrict__ A,
                        const float* __restrict__ biases,
                        const float* __restrict__ attn_self,
                        const float* __restrict__ attn_neigh,
                        float* __restrict__ out) {
    extern __shared__ float sm2[];
    float*  feats_s = sm2;                         // 512*66
    float*  a_s_s   = sm2 + Nn * FPAD;             // 512
    float*  a_n_s   = a_s_s + Nn;                  // 512
    float2* wbuf    = reinterpret_cast<float2*>(a_n_s + Nn);  // 16 * 512 float2

    const int tid  = threadIdx.x;
    const int lane = tid & 31;
    const int wid  = tid >> 5;
    const int chunk = blockIdx.x, h = blockIdx.y, b = blockIdx.z;
    const size_t bh = (size_t)b * Hh + h;
    const float* feats_g = g_feats + bh * Nn * Cc;

    // load feats tile (16384 float2) into padded SMEM
    #pragma unroll
    for (int it = 0; it < 32; ++it) {
        int idx = tid + it * 512;          // float2 index
        int j = idx >> 5, c2 = idx & 31;
        float2 v = reinterpret_cast<const float2*>(feats_g)[idx];
        *reinterpret_cast<float2*>(&feats_s[j * FPAD + c2 * 2]) = v;
    }

    float2 asv = reinterpret_cast<const float2*>(attn_self  + h * Cc)[lane];
    float2 anv = reinterpret_cast<const float2*>(attn_neigh + h * Cc)[lane];
    float2 bsv = reinterpret_cast<const float2*>(biases     + h * Cc)[lane];
    __syncthreads();

    // a_s[n] = feats[n,:].attn_self ; a_n[n] = feats[n,:].attn_neigh
    for (int t = 0; t < 32; ++t) {
        int n = wid * 32 + t;
        float2 fv = *reinterpret_cast<const float2*>(&feats_s[n * FPAD + 2 * lane]);
        float ds = fv.x * asv.x + fv.y * asv.y;
        float dn = fv.x * anv.x + fv.y * anv.y;
        #pragma unroll
        for (int o = 16; o; o >>= 1) {
            ds += __shfl_xor_sync(0xffffffffu, ds, o);
            dn += __shfl_xor_sync(0xffffffffu, dn, o);
        }
        if (lane == 0) { a_s_s[n] = ds; a_n_s[n] = dn; }
    }
    __syncthreads();

    float2* mybuf = wbuf + (size_t)wid * Nn;
    const float* Abase = A + ((size_t)b * Nn + chunk * ROWS) * Nn;
    const unsigned ltmask = (1u << lane) - 1u;

    for (int t = 0; t < ROWS / 16; ++t) {
        const int il = wid + t * 16;
        const int i  = chunk * ROWS + il;
        const float* Arow = Abase + (size_t)il * Nn;
        const float a_si = a_s_s[i];

        float lv[16];
        unsigned pmask = 0;
        #pragma unroll
        for (int k = 0; k < 16; ++k) {
            int j = lane + (k << 5);
            float a = Arow[j];
            float l = a_si + a_n_s[j];
            l = l > 0.f ? l : 0.2f * l;          // LeakyReLU(0.2)
            bool p = (a != 0.f);
            pmask |= (unsigned)p << k;
            lv[k] = p ? l : -1e30f;
        }
        // row max (only unmasked can win; self-loop guarantees one exists)
        float m = lv[0];
        #pragma unroll
        for (int k = 1; k < 16; ++k) m = fmaxf(m, lv[k]);
        #pragma unroll
        for (int o = 16; o; o >>= 1) m = fmaxf(m, __shfl_xor_sync(0xffffffffu, m, o));
        // exp only for unmasked entries (MUFU savings ~19x)
        float s = 0.f;
        #pragma unroll
        for (int k = 0; k < 16; ++k) {
            float w = ((pmask >> k) & 1u) ? __expf(lv[k] - m) : 0.f;
            lv[k] = w;
            s += w;
        }
        #pragma unroll
        for (int o = 16; o; o >>= 1) s += __shfl_xor_sync(0xffffffffu, s, o);
        const float inv = 1.f / s;

        // compact (j, w) pairs into per-warp smem buffer
        int base = 0;
        #pragma unroll
        for (int k = 0; k < 16; ++k) {
            bool p = (pmask >> k) & 1u;
            unsigned bal = __ballot_sync(0xffffffffu, p);
            if (p) {
                int pos = base + __popc(bal & ltmask);
                mybuf[pos] = make_float2(
                    __uint_as_float((unsigned)(lane + (k << 5))), lv[k]);
            }
            base += __popc(bal);
        }
        __syncwarp();

        // sparse accumulate: ~27 entries instead of 512
        float2 acc = make_float2(0.f, 0.f);
        int tt = 0;
        for (; tt + 4 <= base; tt += 4) {
            float2 e0 = mybuf[tt + 0], e1 = mybuf[tt + 1];
            float2 e2 = mybuf[tt + 2], e3 = mybuf[tt + 3];
            float2 f0 = *reinterpret_cast<const float2*>(
                &feats_s[__float_as_uint(e0.x) * FPAD + 2 * lane]);
            float2 f1 = *reinterpret_cast<const float2*>(
                &feats_s[__float_as_uint(e1.x) * FPAD + 2 * lane]);
            float2 f2 = *reinterpret_cast<const float2*>(
                &feats_s[__float_as_uint(e2.x) * FPAD + 2 * lane]);
            float2 f3 = *reinterpret_cast<const float2*>(
                &feats_s[__float_as_uint(e3.x) * FPAD + 2 * lane]);
            acc.x += e0.y * f0.x; acc.y += e0.y * f0.y;
            acc.x += e1.y * f1.x; acc.y += e1.y * f1.y;
            acc.x += e2.y * f2.x; acc.y += e2.y * f2.y;
            acc.x += e3.y * f3.x; acc.y += e3.y * f3.y;
        }
        for (; tt < base; ++tt) {
            float2 e = mybuf[tt];
            float2 fv = *reinterpret_cast<const float2*>(
                &feats_s[__float_as_uint(e.x) * FPAD + 2 * lane]);
            acc.x += e.y * fv.x; acc.y += e.y * fv.y;
        }
        __syncwarp();   // protect buffer before next row reuses it

        // relu(agg-half) == relu(out_h) — maxpool aggregate collapses (see analysis)
        float2 o;
        o.x = fmaxf(acc.x * inv + bsv.x, 0.f);
        o.y = fmaxf(acc.y * inv + bsv.y, 0.f);
        reinterpret_cast<float2*>(
            out + ((size_t)(b * Nn) + i) * OUTW + Hh * Cc + h * Cc)[lane] = o;
    }
}

// ---------------------------------------------------------------------------
extern "C" void kernel_launch(void* const* d_in, const int* in_sizes, int n_in,
                              void* d_out, int out_size) {
    (void)in_sizes; (void)n_in; (void)out_size;
    const float* X          = (const float*)d_in[0];
    const float* A          = (const float*)d_in[1];
    const float* kernels    = (const float*)d_in[2];
    const float* biases     = (const float*)d_in[3];
    const float* attn_self  = (const float*)d_in[4];
    const float* attn_neigh = (const float*)d_in[5];
    float* out = (float*)d_out;

    const int smem1 = (Ff * Cc + 64 * 132) * 4;                          // 66560 B
    const int smem2 = (Nn * FPAD + 2 * Nn) * 4 + 16 * Nn * 8;           // 204800 B
    cudaFuncSetAttribute(k1_proj, cudaFuncAttributeMaxDynamicSharedMemorySize, smem1);
    cudaFuncSetAttribute(k2_attn, cudaFuncAttributeMaxDynamicSharedMemorySize, smem2);

    k1_proj<<<dim3(Nn / 64, Hh, Bb), 256, smem1>>>(X, kernels, out);
    k2_attn<<<dim3(Nn / ROWS, Hh, Bb), 512, smem2>>>(A, biases, attn_self, attn_neigh, out);
}